// round 1
// baseline (speedup 1.0000x reference)
#include <cuda_runtime.h>
#include <math.h>

#define EMBED   192
#define NHEADS  8
#define HDIM    24
#define BATCH   32
#define SEQ     1024
#define MROWS   (BATCH * SEQ)   // 32768

// Scratch (no allocations allowed in kernel_launch; module globals are fine)
__device__ float g_qkv[(size_t)MROWS * 3 * EMBED];   // [32768, 576]  Q|K|V packed per row
__device__ float g_attn[(size_t)MROWS * EMBED];      // [32768, 192]  attention output [b,n,h,d]

// ---------------------------------------------------------------------------
// Generic tiled GEMM: C[M,N] = A[M,K] @ B[K,N] + bias[N]
// BM=BN=64, BK=16, 256 threads, 4x4 microtile per thread.
// All problem dims are exact multiples of the tile sizes — no guards.
// ---------------------------------------------------------------------------
__global__ __launch_bounds__(256)
void gemm_bias_kernel(const float* __restrict__ A, const float* __restrict__ Bm,
                      const float* __restrict__ bias, float* __restrict__ C,
                      int M, int Nn, int K) {
    constexpr int BM = 64, BN = 64, BK = 16;
    __shared__ float As[BM][BK + 1];   // +1 pad: avoid 16-way conflicts on As[.][kk]
    __shared__ float Bs[BK][BN];

    const int tid = threadIdx.x;
    const int tx = tid & 15;           // 16 thread columns
    const int ty = tid >> 4;           // 16 thread rows
    const int rowBase = blockIdx.y * BM;
    const int colBase = blockIdx.x * BN;

    float acc[4][4] = {};

    for (int k0 = 0; k0 < K; k0 += BK) {
        // Load A tile: 64x16 = 1024 elems, 4 per thread
        #pragma unroll
        for (int i = 0; i < (BM * BK) / 256; i++) {
            int li = tid + i * 256;
            int r = li / BK, c = li % BK;
            As[r][c] = A[(size_t)(rowBase + r) * K + (k0 + c)];
        }
        // Load B tile: 16x64 = 1024 elems, 4 per thread (64-wide coalesced)
        #pragma unroll
        for (int i = 0; i < (BK * BN) / 256; i++) {
            int li = tid + i * 256;
            int r = li / BN, c = li % BN;
            Bs[r][c] = Bm[(size_t)(k0 + r) * Nn + (colBase + c)];
        }
        __syncthreads();

        #pragma unroll
        for (int kk = 0; kk < BK; kk++) {
            float a[4], b[4];
            #pragma unroll
            for (int m = 0; m < 4; m++) a[m] = As[ty * 4 + m][kk];
            #pragma unroll
            for (int n = 0; n < 4; n++) b[n] = Bs[kk][tx * 4 + n];
            #pragma unroll
            for (int m = 0; m < 4; m++)
                #pragma unroll
                for (int n = 0; n < 4; n++)
                    acc[m][n] += a[m] * b[n];
        }
        __syncthreads();
    }

    #pragma unroll
    for (int m = 0; m < 4; m++) {
        int gm = rowBase + ty * 4 + m;
        #pragma unroll
        for (int n = 0; n < 4; n++) {
            int gn = colBase + tx * 4 + n;
            C[(size_t)gm * Nn + gn] = acc[m][n] + bias[gn];
        }
    }
}

// ---------------------------------------------------------------------------
// Flash attention: one block per (b, h, q-tile of 128), one query per thread.
// Online softmax in log2 domain; K/V staged through smem in 32-key chunks.
// All 128 threads read the same smem address per inner step -> broadcast.
// ---------------------------------------------------------------------------
__global__ __launch_bounds__(128)
void attn_kernel() {
    const int qt  = blockIdx.x & 7;         // 8 q-tiles of 128
    const int bh  = blockIdx.x >> 3;        // [0, 256)
    const int b   = bh >> 3;
    const int h   = bh & 7;
    const int tid = threadIdx.x;
    const int row = qt * 128 + tid;         // query index in [0, 1024)

    // scale * log2(e): softmax computed in base-2
    const float scale = 1.44269504088896340736f * rsqrtf((float)HDIM);

    float q[HDIM];
    const float* qptr = g_qkv + ((size_t)(b * SEQ + row)) * (3 * EMBED) + h * HDIM;
    #pragma unroll
    for (int d = 0; d < HDIM; d++) q[d] = qptr[d] * scale;

    float m = -INFINITY, l = 0.f;
    float o[HDIM];
    #pragma unroll
    for (int d = 0; d < HDIM; d++) o[d] = 0.f;

    __shared__ float Ks[32 * HDIM];
    __shared__ float Vs[32 * HDIM];

    for (int kc = 0; kc < SEQ / 32; kc++) {
        const int j0 = kc * 32;
        __syncthreads();
        // cooperative load of 32 keys + values (768 floats each)
        for (int i = tid; i < 32 * HDIM; i += 128) {
            int j = i / HDIM, d = i % HDIM;
            size_t base = ((size_t)(b * SEQ + j0 + j)) * (3 * EMBED) + h * HDIM + d;
            Ks[i] = g_qkv[base + EMBED];         // K block
            Vs[i] = g_qkv[base + 2 * EMBED];     // V block
        }
        __syncthreads();

        float s[32];
        float cmax = -INFINITY;
        #pragma unroll
        for (int j = 0; j < 32; j++) {
            float acc = 0.f;
            #pragma unroll
            for (int d = 0; d < HDIM; d++) acc += q[d] * Ks[j * HDIM + d];
            s[j] = acc;
            cmax = fmaxf(cmax, acc);
        }

        const float mnew = fmaxf(m, cmax);
        const float corr = exp2f(m - mnew);      // first iter: exp2(-inf) = 0
        l *= corr;
        #pragma unroll
        for (int d = 0; d < HDIM; d++) o[d] *= corr;

        #pragma unroll
        for (int j = 0; j < 32; j++) {
            const float p = exp2f(s[j] - mnew);
            l += p;
            #pragma unroll
            for (int d = 0; d < HDIM; d++) o[d] += p * Vs[j * HDIM + d];
        }
        m = mnew;
    }

    const float inv = 1.f / l;
    float* optr = g_attn + ((size_t)(b * SEQ + row)) * EMBED + h * HDIM;
    #pragma unroll
    for (int d = 0; d < HDIM; d++) optr[d] = o[d] * inv;
}

// ---------------------------------------------------------------------------
extern "C" void kernel_launch(void* const* d_in, const int* in_sizes, int n_in,
                              void* d_out, int out_size) {
    const float* x     = (const float*)d_in[0];   // [32, 1024, 192]
    const float* Wqkv  = (const float*)d_in[1];   // [192, 576]
    const float* bqkv  = (const float*)d_in[2];   // [576]
    const float* Wproj = (const float*)d_in[3];   // [192, 192]
    const float* bproj = (const float*)d_in[4];   // [192]
    float* out = (float*)d_out;                   // [32, 1024, 192]

    float *qkv_ptr, *attn_ptr;
    cudaGetSymbolAddress((void**)&qkv_ptr,  g_qkv);
    cudaGetSymbolAddress((void**)&attn_ptr, g_attn);

    // 1) QKV projection: [32768,192] @ [192,576] + b
    {
        dim3 grid(3 * EMBED / 64, MROWS / 64);
        gemm_bias_kernel<<<grid, 256>>>(x, Wqkv, bqkv, qkv_ptr, MROWS, 3 * EMBED, EMBED);
    }
    // 2) Attention -> g_attn in [b, n, h, d] layout
    {
        attn_kernel<<<BATCH * NHEADS * (SEQ / 128), 128>>>();
    }
    // 3) Output projection: [32768,192] @ [192,192] + b
    {
        dim3 grid(EMBED / 64, MROWS / 64);
        gemm_bias_kernel<<<grid, 256>>>(attn_ptr, Wproj, bproj, out, MROWS, EMBED, EMBED);
    }
}